// round 4
// baseline (speedup 1.0000x reference)
#include <cuda_runtime.h>

#define N_PTS 40000
#define KNB   32
#define PKP   15
#define CIN   128
#define MID   64
#define COUT  256
#define EPSV  1e-5f
#define INV_EXT 20.0f   // 1 / 0.05
#define WFS   968       // padded wf row stride (floats)

// Scratch (allocation-free rule: __device__ globals)
__device__ float g_x[N_PTS * MID];   // lrelu(bn1(features @ W1))
__device__ float g_y[N_PTS * MID];   // lrelu(KPConv output)

__device__ __forceinline__ float lrelu(float x) { return x >= 0.f ? x : 0.1f * x; }

// acc[i][j] += a_i * b_j
#define FMA16(ACC, a, bq) \
    ACC[0][0] = fmaf(a.x, bq.x, ACC[0][0]); ACC[0][1] = fmaf(a.x, bq.y, ACC[0][1]); \
    ACC[0][2] = fmaf(a.x, bq.z, ACC[0][2]); ACC[0][3] = fmaf(a.x, bq.w, ACC[0][3]); \
    ACC[1][0] = fmaf(a.y, bq.x, ACC[1][0]); ACC[1][1] = fmaf(a.y, bq.y, ACC[1][1]); \
    ACC[1][2] = fmaf(a.y, bq.z, ACC[1][2]); ACC[1][3] = fmaf(a.y, bq.w, ACC[1][3]); \
    ACC[2][0] = fmaf(a.z, bq.x, ACC[2][0]); ACC[2][1] = fmaf(a.z, bq.y, ACC[2][1]); \
    ACC[2][2] = fmaf(a.z, bq.z, ACC[2][2]); ACC[2][3] = fmaf(a.z, bq.w, ACC[2][3]); \
    ACC[3][0] = fmaf(a.w, bq.x, ACC[3][0]); ACC[3][1] = fmaf(a.w, bq.y, ACC[3][1]); \
    ACC[3][2] = fmaf(a.w, bq.z, ACC[3][2]); ACC[3][3] = fmaf(a.w, bq.w, ACC[3][3]);

// ---------------------------------------------------------------------------
// Kernel 1: g_x = lrelu(bn1(features @ W1))     [40000,128] x [128,64]
// ---------------------------------------------------------------------------
__global__ __launch_bounds__(256) void k1_gemm(
    const float* __restrict__ F, const float* __restrict__ W1,
    const float* __restrict__ gg, const float* __restrict__ bb,
    const float* __restrict__ mm, const float* __restrict__ vv)
{
    __shared__ float  As[64][68];     // [k][m], padded
    __shared__ float4 Bs[64][16];     // [k][n/4]

    const int tid  = threadIdx.x;
    const int m0   = blockIdx.x * 64;
    const int tr   = tid >> 4;
    const int tc   = tid & 15;
    const int lrow = tid >> 2;
    const int kb   = (tid & 3) * 16;

    float acc[4][4] = {};

    for (int ch = 0; ch < 2; ch++) {
        const float* Ap = F + (size_t)(m0 + lrow) * CIN + ch * 64 + kb;
        #pragma unroll
        for (int j = 0; j < 4; j++) {
            float4 f = *(const float4*)(Ap + j * 4);
            As[kb + j*4 + 0][lrow] = f.x;
            As[kb + j*4 + 1][lrow] = f.y;
            As[kb + j*4 + 2][lrow] = f.z;
            As[kb + j*4 + 3][lrow] = f.w;
        }
        const float* Bp = W1 + (size_t)(ch * 64 + lrow) * MID + kb;
        #pragma unroll
        for (int j = 0; j < 4; j++)
            Bs[lrow][(kb >> 2) + j] = *(const float4*)(Bp + j * 4);
        __syncthreads();

        #pragma unroll 8
        for (int kk = 0; kk < 64; kk++) {
            float4 a  = *(const float4*)&As[kk][tr * 4];
            float4 bq = Bs[kk][tc];
            FMA16(acc, a, bq)
        }
        __syncthreads();
    }

    float s[4], o[4];
    #pragma unroll
    for (int j = 0; j < 4; j++) {
        int n = tc * 4 + j;
        s[j] = gg[n] * rsqrtf(vv[n] + EPSV);
        o[j] = bb[n] - mm[n] * s[j];
    }
    #pragma unroll
    for (int i = 0; i < 4; i++) {
        float4 r;
        r.x = lrelu(fmaf(acc[i][0], s[0], o[0]));
        r.y = lrelu(fmaf(acc[i][1], s[1], o[1]));
        r.z = lrelu(fmaf(acc[i][2], s[2], o[2]));
        r.w = lrelu(fmaf(acc[i][3], s[3], o[3]));
        *(float4*)&g_x[(size_t)(m0 + tr * 4 + i) * MID + tc * 4] = r;
    }
}

// ---------------------------------------------------------------------------
// Kernel 2: KPConv. 8 points/block, 256 threads, grid 5000.
//  phase1: influence h[8][32][16] (float4-packed) in smem
//  phase2: wf[n][p][c] = sum_k h[n][k][p] * g_x[nbr[n][k]][c]  (regs -> smem)
//  phase3: y[n][d] = sum_i wf[n][i] * Wkp[i][d]; 2 points/thread per Wkp load,
//          i split in 4 quarters + smem reduction; lrelu -> g_y
// ---------------------------------------------------------------------------
__global__ __launch_bounds__(256) void k2_kpconv(
    const float* __restrict__ points, const int* __restrict__ nbr,
    const float* __restrict__ kp,     const float* __restrict__ Wkp)
{
    __shared__ float4 h_sh[8][32][4];        // 16 KB  (h[n][k][p], p packed in 4xfloat4)
    __shared__ int    idx_sh[8][32];         // 1 KB
    __shared__ float  wf_sh[8 * WFS];        // 30.3 KB (row stride 968)
    __shared__ float  kp_sh[PKP * 3];

    const int tid  = threadIdx.x;
    const int base = blockIdx.x * 8;

    if (tid < PKP * 3) kp_sh[tid] = kp[tid];

    // ---- phase 1: influences ----
    {
        const int nl = tid >> 5;
        const int k  = tid & 31;
        const int ng = base + nl;
        const int id = nbr[ng * KNB + k];
        idx_sh[nl][k] = id;
        const float ax = points[id * 3 + 0] - points[ng * 3 + 0];
        const float ay = points[id * 3 + 1] - points[ng * 3 + 1];
        const float az = points[id * 3 + 2] - points[ng * 3 + 2];
        __syncthreads();   // kp_sh ready

        float hv[16];
        #pragma unroll
        for (int p = 0; p < PKP; p++) {
            float dx = ax - kp_sh[p * 3 + 0];
            float dy = ay - kp_sh[p * 3 + 1];
            float dz = az - kp_sh[p * 3 + 2];
            float dist = sqrtf(fmaf(dx, dx, fmaf(dy, dy, dz * dz)));
            hv[p] = fmaxf(0.f, 1.f - dist * INV_EXT);
        }
        hv[15] = 0.f;
        #pragma unroll
        for (int j = 0; j < 4; j++)
            h_sh[nl][k][j] = make_float4(hv[j*4+0], hv[j*4+1], hv[j*4+2], hv[j*4+3]);
    }
    __syncthreads();   // h + idx ready

    // ---- phase 2: wf accumulation (2 channels / thread, float4 h loads) ----
    {
        const int c2 = (tid & 31) * 2;
        const int n2 = tid >> 5;
        float wf0[PKP] = {}, wf1[PKP] = {};
        #pragma unroll 2
        for (int kk = 0; kk < KNB; kk++) {
            const int nid = idx_sh[n2][kk];
            const float2 fn = *(const float2*)&g_x[(size_t)nid * MID + c2];
            const float4 h0 = h_sh[n2][kk][0];
            const float4 h1 = h_sh[n2][kk][1];
            const float4 h2 = h_sh[n2][kk][2];
            const float4 h3 = h_sh[n2][kk][3];
            const float hh[15] = { h0.x,h0.y,h0.z,h0.w, h1.x,h1.y,h1.z,h1.w,
                                   h2.x,h2.y,h2.z,h2.w, h3.x,h3.y,h3.z };
            #pragma unroll
            for (int p = 0; p < PKP; p++) {
                wf0[p] = fmaf(hh[p], fn.x, wf0[p]);
                wf1[p] = fmaf(hh[p], fn.y, wf1[p]);
            }
        }
        #pragma unroll
        for (int p = 0; p < PKP; p++)
            *(float2*)&wf_sh[n2 * WFS + p * MID + c2] = make_float2(wf0[p], wf1[p]);
    }
    __syncthreads();   // wf ready; h_sh free for reuse

    // ---- phase 3: y = wf . Wkp ----
    {
        const int dv = tid & 15;          // out-channel group (4 ch)
        const int pp = (tid >> 4) & 3;    // point pair -> points 2pp, 2pp+1
        const int qq = tid >> 6;          // quarter of i-range (240 each)

        const float*  wfp0 = wf_sh + (2*pp + 0) * WFS + qq * 240;
        const float*  wfp1 = wf_sh + (2*pp + 1) * WFS + qq * 240;
        const float4* wq   = (const float4*)Wkp + (size_t)(qq * 240) * 16 + dv;

        float a0=0.f,a1=0.f,a2=0.f,a3=0.f;   // point 2pp
        float b0=0.f,b1=0.f,b2=0.f,b3=0.f;   // point 2pp+1
        #pragma unroll 4
        for (int i = 0; i < 240; i++) {
            float4 w = wq[(size_t)i * 16];
            float  s0 = wfp0[i];
            float  s1 = wfp1[i];
            a0 = fmaf(s0, w.x, a0); a1 = fmaf(s0, w.y, a1);
            a2 = fmaf(s0, w.z, a2); a3 = fmaf(s0, w.w, a3);
            b0 = fmaf(s1, w.x, b0); b1 = fmaf(s1, w.y, b1);
            b2 = fmaf(s1, w.z, b2); b3 = fmaf(s1, w.w, b3);
        }
        float* red = (float*)h_sh;   // reuse: 4 qq x 8 pt x 64 = 2048 floats
        *(float4*)&red[(qq * 8 + 2*pp + 0) * 64 + dv * 4] = make_float4(a0,a1,a2,a3);
        *(float4*)&red[(qq * 8 + 2*pp + 1) * 64 + dv * 4] = make_float4(b0,b1,b2,b3);
        __syncthreads();

        if (tid < 128) {
            const int pt = tid >> 4;
            const int d4 = (tid & 15) * 4;
            float4 s = *(const float4*)&red[pt * 64 + d4];
            #pragma unroll
            for (int q = 1; q < 4; q++) {
                float4 t = *(const float4*)&red[(q * 8 + pt) * 64 + d4];
                s.x += t.x; s.y += t.y; s.z += t.z; s.w += t.w;
            }
            float4 r;
            r.x = lrelu(s.x); r.y = lrelu(s.y); r.z = lrelu(s.z); r.w = lrelu(s.w);
            *(float4*)&g_y[(size_t)(base + pt) * MID + d4] = r;
        }
    }
}

// ---------------------------------------------------------------------------
// Kernel 3: out = lrelu( lrelu(bn2(g_y @ W2)) + lrelu(bns(F @ Ws)) )
// ---------------------------------------------------------------------------
__global__ __launch_bounds__(256) void k3_out(
    const float* __restrict__ F,
    const float* __restrict__ W2,
    const float* __restrict__ b2g, const float* __restrict__ b2b,
    const float* __restrict__ b2m, const float* __restrict__ b2v,
    const float* __restrict__ Ws,
    const float* __restrict__ bsg, const float* __restrict__ bsb,
    const float* __restrict__ bsm, const float* __restrict__ bsv,
    float* __restrict__ out)
{
    __shared__ float  As[64][68];
    __shared__ float4 Bs[64][16];

    const int tid  = threadIdx.x;
    const int m0   = blockIdx.x * 64;
    const int n0   = blockIdx.y * 64;
    const int tr   = tid >> 4;
    const int tc   = tid & 15;
    const int lrow = tid >> 2;
    const int kb   = (tid & 3) * 16;

    float accY[4][4] = {};
    float accS[4][4] = {};

#define K3_CHUNK(APTR, LDA, KOFS, BPTR, ACC)                                     \
    {                                                                            \
        const float* Ap = (APTR) + (size_t)(m0 + lrow) * (LDA) + (KOFS) + kb;    \
        _Pragma("unroll")                                                        \
        for (int j = 0; j < 4; j++) {                                            \
            float4 f = *(const float4*)(Ap + j * 4);                             \
            As[kb + j*4 + 0][lrow] = f.x;                                        \
            As[kb + j*4 + 1][lrow] = f.y;                                        \
            As[kb + j*4 + 2][lrow] = f.z;                                        \
            As[kb + j*4 + 3][lrow] = f.w;                                        \
        }                                                                        \
        const float* Bp = (BPTR) + (size_t)((KOFS) + lrow) * COUT + n0 + kb;     \
        _Pragma("unroll")                                                        \
        for (int j = 0; j < 4; j++)                                              \
            Bs[lrow][(kb >> 2) + j] = *(const float4*)(Bp + j * 4);              \
        __syncthreads();                                                         \
        _Pragma("unroll 8")                                                      \
        for (int kk = 0; kk < 64; kk++) {                                        \
            float4 a  = *(const float4*)&As[kk][tr * 4];                         \
            float4 bq = Bs[kk][tc];                                              \
            FMA16(ACC, a, bq)                                                    \
        }                                                                        \
        __syncthreads();                                                         \
    }

    K3_CHUNK(g_y, MID, 0,  W2, accY)
    K3_CHUNK(F,   CIN, 0,  Ws, accS)
    K3_CHUNK(F,   CIN, 64, Ws, accS)
#undef K3_CHUNK

    float s2[4], o2[4], ss[4], os[4];
    #pragma unroll
    for (int j = 0; j < 4; j++) {
        int n = n0 + tc * 4 + j;
        s2[j] = b2g[n] * rsqrtf(b2v[n] + EPSV);
        o2[j] = b2b[n] - b2m[n] * s2[j];
        ss[j] = bsg[n] * rsqrtf(bsv[n] + EPSV);
        os[j] = bsb[n] - bsm[n] * ss[j];
    }
    #pragma unroll
    for (int i = 0; i < 4; i++) {
        float4 r;
        r.x = lrelu(lrelu(fmaf(accY[i][0], s2[0], o2[0])) + lrelu(fmaf(accS[i][0], ss[0], os[0])));
        r.y = lrelu(lrelu(fmaf(accY[i][1], s2[1], o2[1])) + lrelu(fmaf(accS[i][1], ss[1], os[1])));
        r.z = lrelu(lrelu(fmaf(accY[i][2], s2[2], o2[2])) + lrelu(fmaf(accS[i][2], ss[2], os[2])));
        r.w = lrelu(lrelu(fmaf(accY[i][3], s2[3], o2[3])) + lrelu(fmaf(accS[i][3], ss[3], os[3])));
        *(float4*)&out[(size_t)(m0 + tr * 4 + i) * COUT + n0 + tc * 4] = r;
    }
}

// ---------------------------------------------------------------------------
extern "C" void kernel_launch(void* const* d_in, const int* in_sizes, int n_in,
                              void* d_out, int out_size)
{
    const float* F    = (const float*)d_in[0];
    const float* pts  = (const float*)d_in[1];
    const int*   nbr  = (const int*)  d_in[2];
    const float* W1   = (const float*)d_in[3];
    const float* b1g  = (const float*)d_in[4];
    const float* b1b  = (const float*)d_in[5];
    const float* b1m  = (const float*)d_in[6];
    const float* b1v  = (const float*)d_in[7];
    const float* kp   = (const float*)d_in[8];
    const float* Wkp  = (const float*)d_in[9];
    const float* W2   = (const float*)d_in[10];
    const float* b2g  = (const float*)d_in[11];
    const float* b2b  = (const float*)d_in[12];
    const float* b2m  = (const float*)d_in[13];
    const float* b2v  = (const float*)d_in[14];
    const float* Ws   = (const float*)d_in[15];
    const float* bsg  = (const float*)d_in[16];
    const float* bsb  = (const float*)d_in[17];
    const float* bsm  = (const float*)d_in[18];
    const float* bsv  = (const float*)d_in[19];
    float* out = (float*)d_out;

    k1_gemm  <<<N_PTS / 64, 256>>>(F, W1, b1g, b1b, b1m, b1v);
    k2_kpconv<<<N_PTS / 8,  256>>>(pts, nbr, kp, Wkp);
    k3_out   <<<dim3(N_PTS / 64, COUT / 64), 256>>>(
        F, W2, b2g, b2b, b2m, b2v, Ws, bsg, bsb, bsm, bsv, out);
}

// round 6
// speedup vs baseline: 1.0015x; 1.0015x over previous
#include <cuda_runtime.h>

#define N_PTS 40000
#define KNB   32
#define PKP   15
#define CIN   128
#define MID   64
#define COUT  256
#define EPSV  1e-5f
#define INV_EXT 20.0f     // 1 / 0.05
#define PTS_BLK 16        // k2 points per block
#define WFS   972         // wf row stride in floats (4*WFS % 32banks = 16 -> conflict-free)
#define SMEM2 (2304 + 32768 + 62208)   // kp/idx | h(16KB red alias) | wf

// Scratch (allocation-free rule: __device__ globals)
__device__ float g_x[N_PTS * MID];   // lrelu(bn1(features @ W1))
__device__ float g_y[N_PTS * MID];   // lrelu(KPConv output)

__device__ __forceinline__ float lrelu(float x) { return x >= 0.f ? x : 0.1f * x; }

// ---------------------------------------------------------------------------
// Kernel 1: g_x = lrelu(bn1(features @ W1))   [40000,128]x[128,64]
// 128 threads, BM=64, BN=64, micro-tile 8x4, K-chunks of 32.
// ---------------------------------------------------------------------------
__global__ __launch_bounds__(128) void k1_gemm(
    const float* __restrict__ F, const float* __restrict__ W1,
    const float* __restrict__ gg, const float* __restrict__ bb,
    const float* __restrict__ mm, const float* __restrict__ vv)
{
    __shared__ float  As[32][68];    // [k][m]
    __shared__ float4 Bs[32][16];    // [k][n/4]

    const int tid  = threadIdx.x;
    const int m0   = blockIdx.x * 64;
    const int tr   = tid >> 4;          // 0..7  -> rows tr*8..
    const int tc   = tid & 15;          // 0..15 -> cols tc*4..
    const int arow = tid >> 1;          // 0..63
    const int akb  = (tid & 1) * 16;    // 0,16
    const int brow = tid >> 2;          // 0..31
    const int bnb  = (tid & 3) * 4;     // 0,4,8,12

    float acc[8][4] = {};

    for (int ch = 0; ch < 4; ch++) {
        const float* Ap = F + (size_t)(m0 + arow) * CIN + ch * 32 + akb;
        #pragma unroll
        for (int j = 0; j < 4; j++) {
            float4 f = *(const float4*)(Ap + j * 4);
            As[akb + j*4 + 0][arow] = f.x;
            As[akb + j*4 + 1][arow] = f.y;
            As[akb + j*4 + 2][arow] = f.z;
            As[akb + j*4 + 3][arow] = f.w;
        }
        const float* Bp = W1 + (size_t)(ch * 32 + brow) * MID + bnb * 4;
        #pragma unroll
        for (int j = 0; j < 4; j++)
            Bs[brow][bnb + j] = *(const float4*)(Bp + j * 4);
        __syncthreads();

        #pragma unroll 8
        for (int k = 0; k < 32; k++) {
            float4 a0 = *(const float4*)&As[k][tr * 8];
            float4 a1 = *(const float4*)&As[k][tr * 8 + 4];
            float4 b  = Bs[k][tc];
            const float av[8] = { a0.x,a0.y,a0.z,a0.w, a1.x,a1.y,a1.z,a1.w };
            #pragma unroll
            for (int i = 0; i < 8; i++) {
                acc[i][0] = fmaf(av[i], b.x, acc[i][0]);
                acc[i][1] = fmaf(av[i], b.y, acc[i][1]);
                acc[i][2] = fmaf(av[i], b.z, acc[i][2]);
                acc[i][3] = fmaf(av[i], b.w, acc[i][3]);
            }
        }
        __syncthreads();
    }

    float s[4], o[4];
    #pragma unroll
    for (int j = 0; j < 4; j++) {
        int n = tc * 4 + j;
        s[j] = gg[n] * rsqrtf(vv[n] + EPSV);
        o[j] = bb[n] - mm[n] * s[j];
    }
    #pragma unroll
    for (int i = 0; i < 8; i++) {
        float4 r;
        r.x = lrelu(fmaf(acc[i][0], s[0], o[0]));
        r.y = lrelu(fmaf(acc[i][1], s[1], o[1]));
        r.z = lrelu(fmaf(acc[i][2], s[2], o[2]));
        r.w = lrelu(fmaf(acc[i][3], s[3], o[3]));
        *(float4*)&g_x[(size_t)(m0 + tr * 8 + i) * MID + tc * 4] = r;
    }
}

// ---------------------------------------------------------------------------
// Kernel 2: KPConv. 16 points/block, 256 threads, grid 2500, dynamic smem.
//  phase1: h[16][32][16] influences (float4-packed)
//  phase2: wf[pt][p*64+c] = sum_k h*g_x   (4 channels/thread)
//  phase3: y = wf . Wkp  (4 points + 4 out-ch per thread per Wkp float4;
//          i-range split in 4 segments of 240 + smem reduction)
// ---------------------------------------------------------------------------
__global__ __launch_bounds__(256) void k2_kpconv(
    const float* __restrict__ points, const int* __restrict__ nbr,
    const float* __restrict__ kp,     const float* __restrict__ Wkp)
{
    extern __shared__ char smem2[];
    float*  kp_sh  = (float*) smem2;                    // 45 floats
    int*    idx_sh = (int*)  (smem2 + 256);             // 512 ints
    float4* h4     = (float4*)(smem2 + 2304);           // 16*32*4 float4 (32KB)
    float*  red    = (float*) (smem2 + 2304);           // alias of h (16KB used)
    float*  wf     = (float*) (smem2 + 2304 + 32768);   // 16*972 floats

    const int tid  = threadIdx.x;
    const int base = blockIdx.x * PTS_BLK;

    if (tid < PKP * 3) kp_sh[tid] = kp[tid];

    // ---- phase 1: influences (2 (pt,k) pairs per thread) ----
    float ax[2], ay[2], az[2];
    #pragma unroll
    for (int e = 0; e < 2; e++) {
        const int ii = tid + e * 256;
        const int nl = ii >> 5, k = ii & 31;
        const int ng = base + nl;
        const int id = nbr[ng * KNB + k];
        idx_sh[ii] = id;
        ax[e] = points[id * 3 + 0] - points[ng * 3 + 0];
        ay[e] = points[id * 3 + 1] - points[ng * 3 + 1];
        az[e] = points[id * 3 + 2] - points[ng * 3 + 2];
    }
    __syncthreads();   // kp_sh ready

    #pragma unroll
    for (int e = 0; e < 2; e++) {
        const int ii = tid + e * 256;
        float hv[16];
        #pragma unroll
        for (int p = 0; p < PKP; p++) {
            float dx = ax[e] - kp_sh[p * 3 + 0];
            float dy = ay[e] - kp_sh[p * 3 + 1];
            float dz = az[e] - kp_sh[p * 3 + 2];
            float dist = sqrtf(fmaf(dx, dx, fmaf(dy, dy, dz * dz)));
            hv[p] = fmaxf(0.f, 1.f - dist * INV_EXT);
        }
        hv[15] = 0.f;
        #pragma unroll
        for (int j = 0; j < 4; j++)
            h4[ii * 4 + j] = make_float4(hv[j*4+0], hv[j*4+1], hv[j*4+2], hv[j*4+3]);
    }
    __syncthreads();   // h + idx ready

    // ---- phase 2: wf accumulation (4 channels / thread) ----
    {
        const int pt  = tid >> 4;          // 0..15
        const int c4  = (tid & 15) * 4;    // channels c4..c4+3
        float4 w4[PKP];
        #pragma unroll
        for (int p = 0; p < PKP; p++) w4[p] = make_float4(0.f, 0.f, 0.f, 0.f);

        for (int kk = 0; kk < KNB; kk++) {
            const int nid = idx_sh[pt * 32 + kk];
            const float4 fn = *(const float4*)&g_x[(size_t)nid * MID + c4];
            const float4 h0 = h4[(pt * 32 + kk) * 4 + 0];
            const float4 h1 = h4[(pt * 32 + kk) * 4 + 1];
            const float4 h2 = h4[(pt * 32 + kk) * 4 + 2];
            const float4 h3 = h4[(pt * 32 + kk) * 4 + 3];
            const float hh[15] = { h0.x,h0.y,h0.z,h0.w, h1.x,h1.y,h1.z,h1.w,
                                   h2.x,h2.y,h2.z,h2.w, h3.x,h3.y,h3.z };
            #pragma unroll
            for (int p = 0; p < PKP; p++) {
                w4[p].x = fmaf(hh[p], fn.x, w4[p].x);
                w4[p].y = fmaf(hh[p], fn.y, w4[p].y);
                w4[p].z = fmaf(hh[p], fn.z, w4[p].z);
                w4[p].w = fmaf(hh[p], fn.w, w4[p].w);
            }
        }
        #pragma unroll
        for (int p = 0; p < PKP; p++)
            *(float4*)&wf[pt * WFS + p * MID + c4] = w4[p];
    }
    __syncthreads();   // wf ready; h region now reusable as `red`

    // ---- phase 3: y = wf . Wkp ----
    {
        const int dv = tid & 15;          // out-channel group (4 ch)
        const int pq = (tid >> 4) & 3;    // point quad -> points 4pq..4pq+3
        const int qq = tid >> 6;          // segment of i (240 each)

        const float* w0 = wf + (pq * 4 + 0) * WFS + qq * 240;
        const float* w1 = wf + (pq * 4 + 1) * WFS + qq * 240;
        const float* w2 = wf + (pq * 4 + 2) * WFS + qq * 240;
        const float* w3 = wf + (pq * 4 + 3) * WFS + qq * 240;
        const float4* wq = (const float4*)Wkp + (size_t)(qq * 240) * 16 + dv;

        float4 a0 = make_float4(0,0,0,0), a1 = a0, a2 = a0, a3 = a0;
        #pragma unroll 4
        for (int i = 0; i < 240; i++) {
            float4 w = wq[(size_t)i * 16];
            float s0 = w0[i], s1 = w1[i], s2 = w2[i], s3 = w3[i];
            a0.x = fmaf(s0, w.x, a0.x); a0.y = fmaf(s0, w.y, a0.y);
            a0.z = fmaf(s0, w.z, a0.z); a0.w = fmaf(s0, w.w, a0.w);
            a1.x = fmaf(s1, w.x, a1.x); a1.y = fmaf(s1, w.y, a1.y);
            a1.z = fmaf(s1, w.z, a1.z); a1.w = fmaf(s1, w.w, a1.w);
            a2.x = fmaf(s2, w.x, a2.x); a2.y = fmaf(s2, w.y, a2.y);
            a2.z = fmaf(s2, w.z, a2.z); a2.w = fmaf(s2, w.w, a2.w);
            a3.x = fmaf(s3, w.x, a3.x); a3.y = fmaf(s3, w.y, a3.y);
            a3.z = fmaf(s3, w.z, a3.z); a3.w = fmaf(s3, w.w, a3.w);
        }
        *(float4*)&red[(qq * 16 + pq * 4 + 0) * 64 + dv * 4] = a0;
        *(float4*)&red[(qq * 16 + pq * 4 + 1) * 64 + dv * 4] = a1;
        *(float4*)&red[(qq * 16 + pq * 4 + 2) * 64 + dv * 4] = a2;
        *(float4*)&red[(qq * 16 + pq * 4 + 3) * 64 + dv * 4] = a3;
        __syncthreads();

        const int pt = tid >> 4;          // 0..15
        const int d4 = (tid & 15) * 4;
        float4 s = *(const float4*)&red[pt * 64 + d4];
        #pragma unroll
        for (int q = 1; q < 4; q++) {
            float4 t = *(const float4*)&red[(q * 16 + pt) * 64 + d4];
            s.x += t.x; s.y += t.y; s.z += t.z; s.w += t.w;
        }
        float4 r;
        r.x = lrelu(s.x); r.y = lrelu(s.y); r.z = lrelu(s.z); r.w = lrelu(s.w);
        *(float4*)&g_y[(size_t)(base + pt) * MID + d4] = r;
    }
}

// ---------------------------------------------------------------------------
// Kernel 3: out = lrelu( lrelu(bn2(g_y @ W2)) + lrelu(bns(F @ Ws)) )
// 256 threads, BM=64, BN=128, micro-tile 8x4, K-chunks of 32, grid (625,2).
// ---------------------------------------------------------------------------
__global__ __launch_bounds__(256) void k3_out(
    const float* __restrict__ F,
    const float* __restrict__ W2,
    const float* __restrict__ b2g, const float* __restrict__ b2b,
    const float* __restrict__ b2m, const float* __restrict__ b2v,
    const float* __restrict__ Ws,
    const float* __restrict__ bsg, const float* __restrict__ bsb,
    const float* __restrict__ bsm, const float* __restrict__ bsv,
    float* __restrict__ out)
{
    __shared__ float  As[32][68];    // [k][m]
    __shared__ float4 Bs[32][32];    // [k][n/4]

    const int tid  = threadIdx.x;
    const int m0   = blockIdx.x * 64;
    const int n0   = blockIdx.y * 128;
    const int tr   = tid >> 5;          // 0..7  rows tr*8..
    const int tc   = tid & 31;          // 0..31 cols tc*4..
    const int arow = tid >> 2;          // 0..63
    const int akb  = (tid & 3) * 8;     // 0,8,16,24
    const int brow = tid >> 3;          // 0..31
    const int bnb  = (tid & 7) * 4;     // 0..28

    float accY[8][4] = {};
    float accS[8][4] = {};

#define K3_CHUNK(APTR, LDA, KOFS, BPTR, ACC)                                     \
    {                                                                            \
        const float* Ap = (APTR) + (size_t)(m0 + arow) * (LDA) + (KOFS) + akb;   \
        _Pragma("unroll")                                                        \
        for (int j = 0; j < 2; j++) {                                            \
            float4 f = *(const float4*)(Ap + j * 4);                             \
            As[akb + j*4 + 0][arow] = f.x;                                       \
            As[akb + j*4 + 1][arow] = f.y;                                       \
            As[akb + j*4 + 2][arow] = f.z;                                       \
            As[akb + j*4 + 3][arow] = f.w;                                       \
        }                                                                        \
        const float* Bp = (BPTR) + (size_t)((KOFS) + brow) * COUT + n0 + bnb * 4;\
        _Pragma("unroll")                                                        \
        for (int j = 0; j < 4; j++)                                              \
            Bs[brow][bnb + j] = *(const float4*)(Bp + j * 4);                    \
        __syncthreads();                                                         \
        _Pragma("unroll 8")                                                      \
        for (int k = 0; k < 32; k++) {                                           \
            float4 a0 = *(const float4*)&As[k][tr * 8];                          \
            float4 a1 = *(const float4*)&As[k][tr * 8 + 4];                      \
            float4 b  = Bs[k][tc];                                               \
            const float av[8] = { a0.x,a0.y,a0.z,a0.w, a1.x,a1.y,a1.z,a1.w };    \
            _Pragma("unroll")                                                    \
            for (int i = 0; i < 8; i++) {                                        \
                ACC[i][0] = fmaf(av[i], b.x, ACC[i][0]);                         \
                ACC[i][1] = fmaf(av[i], b.y, ACC[i][1]);                         \
                ACC[i][2] = fmaf(av[i], b.z, ACC[i][2]);                         \
                ACC[i][3] = fmaf(av[i], b.w, ACC[i][3]);                         \
            }                                                                    \
        }                                                                        \
        __syncthreads();                                                         \
    }

    K3_CHUNK(g_y, MID, 0,   W2, accY)
    K3_CHUNK(g_y, MID, 32,  W2, accY)
    K3_CHUNK(F,   CIN, 0,   Ws, accS)
    K3_CHUNK(F,   CIN, 32,  Ws, accS)
    K3_CHUNK(F,   CIN, 64,  Ws, accS)
    K3_CHUNK(F,   CIN, 96,  Ws, accS)
#undef K3_CHUNK

    float s2[4], o2[4], ss[4], os[4];
    #pragma unroll
    for (int j = 0; j < 4; j++) {
        int n = n0 + tc * 4 + j;
        s2[j] = b2g[n] * rsqrtf(b2v[n] + EPSV);
        o2[j] = b2b[n] - b2m[n] * s2[j];
        ss[j] = bsg[n] * rsqrtf(bsv[n] + EPSV);
        os[j] = bsb[n] - bsm[n] * ss[j];
    }
    #pragma unroll
    for (int i = 0; i < 8; i++) {
        float4 r;
        r.x = lrelu(lrelu(fmaf(accY[i][0], s2[0], o2[0])) + lrelu(fmaf(accS[i][0], ss[0], os[0])));
        r.y = lrelu(lrelu(fmaf(accY[i][1], s2[1], o2[1])) + lrelu(fmaf(accS[i][1], ss[1], os[1])));
        r.z = lrelu(lrelu(fmaf(accY[i][2], s2[2], o2[2])) + lrelu(fmaf(accS[i][2], ss[2], os[2])));
        r.w = lrelu(lrelu(fmaf(accY[i][3], s2[3], o2[3])) + lrelu(fmaf(accS[i][3], ss[3], os[3])));
        *(float4*)&out[(size_t)(m0 + tr * 8 + i) * COUT + n0 + tc * 4] = r;
    }
}

// ---------------------------------------------------------------------------
extern "C" void kernel_launch(void* const* d_in, const int* in_sizes, int n_in,
                              void* d_out, int out_size)
{
    const float* F    = (const float*)d_in[0];
    const float* pts  = (const float*)d_in[1];
    const int*   nbr  = (const int*)  d_in[2];
    const float* W1   = (const float*)d_in[3];
    const float* b1g  = (const float*)d_in[4];
    const float* b1b  = (const float*)d_in[5];
    const float* b1m  = (const float*)d_in[6];
    const float* b1v  = (const float*)d_in[7];
    const float* kp   = (const float*)d_in[8];
    const float* Wkp  = (const float*)d_in[9];
    const float* W2   = (const float*)d_in[10];
    const float* b2g  = (const float*)d_in[11];
    const float* b2b  = (const float*)d_in[12];
    const float* b2m  = (const float*)d_in[13];
    const float* b2v  = (const float*)d_in[14];
    const float* Ws   = (const float*)d_in[15];
    const float* bsg  = (const float*)d_in[16];
    const float* bsb  = (const float*)d_in[17];
    const float* bsm  = (const float*)d_in[18];
    const float* bsv  = (const float*)d_in[19];
    float* out = (float*)d_out;

    cudaFuncSetAttribute(k2_kpconv, cudaFuncAttributeMaxDynamicSharedMemorySize, SMEM2);

    k1_gemm  <<<N_PTS / 64, 128>>>(F, W1, b1g, b1b, b1m, b1v);
    k2_kpconv<<<N_PTS / PTS_BLK, 256, SMEM2>>>(pts, nbr, kp, Wkp);
    k3_out   <<<dim3(N_PTS / 64, COUT / 128), 256>>>(
        F, W2, b2g, b2b, b2m, b2v, Ws, bsg, bsb, bsm, bsv, out);
}